// round 5
// baseline (speedup 1.0000x reference)
#include <cuda_runtime.h>

// SharedSharedLoss: mean off-diagonal pairwise squared L2 distance / C.
// Identity: sum_{i,j} ||a_i - a_j||^2 = 2N * S2 - 2 * ||colsum||^2
// pass1: 16 col-strips x 8 row-chunks = 128 blocks x 512 thr; 8 float4 loads
//        per thread; shuffle+1-barrier reduce; writes 16 KB of partials.
// pass2: tiny L2-resident reduce + scalar combine (separate launch — no
//        threadfence/atomic tail on pass1's critical path).

#define N_ROWS 4096
#define N_COLS 512
#define N_COLS4 128                  // float4 groups per row
#define N_STRIPS 16                  // column strips of 32 cols (8 float4 groups)
#define N_CHUNKS 8                   // row chunks of 512 rows
#define GRID1 (N_STRIPS * N_CHUNKS)  // 128 blocks
#define BLK 512                      // 8 col-groups x 64 row-lanes
#define ROWS_PER_CHUNK (N_ROWS / N_CHUNKS)   // 512
#define ROW_LANES 64
#define LPT (ROWS_PER_CHUNK / ROW_LANES)     // 8 loads per thread
#define NWARPS (BLK / 32)                    // 16

// Deterministic scratch (no float atomics anywhere).
__device__ float g_colpart[GRID1 * 32];   // [rc*16+cs][32 cols] = 16 KB
__device__ float g_s2part[GRID1];

__global__ __launch_bounds__(BLK, 1) void pass1_kernel(const float* __restrict__ A) {
    const int t  = threadIdx.x;
    const int g  = t & 7;            // float4 group within strip (0..7)
    const int r0 = t >> 3;           // row lane (0..63)
    const int b  = blockIdx.x;
    const int cs = b & (N_STRIPS - 1);   // column strip
    const int rc = b >> 4;               // row chunk

    const float4* __restrict__ A4 = reinterpret_cast<const float4*>(A);

    // ---- Streaming: 512 rows x 32 cols per block, 8 independent loads ----
    const int base = (rc * ROWS_PER_CHUNK + r0) * N_COLS4 + cs * 8 + g;
    float4 v[LPT];
    #pragma unroll
    for (int i = 0; i < LPT; i++)
        v[i] = A4[base + i * ROW_LANES * N_COLS4];

    float4 c = make_float4(0.f, 0.f, 0.f, 0.f);
    float s2 = 0.f;
    #pragma unroll
    for (int i = 0; i < LPT; i++) {
        c.x += v[i].x; c.y += v[i].y; c.z += v[i].z; c.w += v[i].w;
        s2 += v[i].x * v[i].x + v[i].y * v[i].y
            + v[i].z * v[i].z + v[i].w * v[i].w;
    }

    // ---- Warp-level reduce ----
    // Lanes with the same group g within a warp differ by 8 in lane id.
    #pragma unroll
    for (int off = 16; off >= 8; off >>= 1) {
        c.x += __shfl_down_sync(0xFFFFFFFFu, c.x, off);
        c.y += __shfl_down_sync(0xFFFFFFFFu, c.y, off);
        c.z += __shfl_down_sync(0xFFFFFFFFu, c.z, off);
        c.w += __shfl_down_sync(0xFFFFFFFFu, c.w, off);
    }
    // Full warp reduce for s2.
    #pragma unroll
    for (int off = 16; off > 0; off >>= 1)
        s2 += __shfl_down_sync(0xFFFFFFFFu, s2, off);

    __shared__ float4 sh[NWARPS * 8];       // [warp][group]
    __shared__ float  warp_s2[NWARPS];
    const int w = t >> 5, lane = t & 31;
    if (lane < 8) sh[w * 8 + lane] = c;     // lane == g for lanes 0..7
    if (lane == 0) warp_s2[w] = s2;
    __syncthreads();

    // ---- Final combine (one barrier, flat 16-way sums) ----
    if (t < 8) {
        float4 acc = make_float4(0.f, 0.f, 0.f, 0.f);
        #pragma unroll
        for (int k = 0; k < NWARPS; k++) {
            float4 m = sh[k * 8 + t];
            acc.x += m.x; acc.y += m.y; acc.z += m.z; acc.w += m.w;
        }
        reinterpret_cast<float4*>(g_colpart)[b * 8 + t] = acc;
    } else if (t == 8) {
        float tot = 0.f;
        #pragma unroll
        for (int k = 0; k < NWARPS; k++) tot += warp_s2[k];
        g_s2part[b] = tot;
    }
}

__global__ __launch_bounds__(512) void pass2_kernel(float* __restrict__ out) {
    const int t = threadIdx.x;       // 0..511 — one column each

    // Column col = cs*32 + local; partial float index = (rc*16+cs)*32 + local
    // = rc*512 + col. Coalesced across threads; 8 independent loads.
    float s = 0.f;
    #pragma unroll
    for (int r = 0; r < N_CHUNKS; r++)
        s += g_colpart[r * N_COLS + t];
    double dnrm = (double)s * (double)s;
    double ds2  = (t < GRID1) ? (double)g_s2part[t] : 0.0;

    // Reduce 512 doubles (16 warps) via shuffles + shared.
    __shared__ double w_nrm[16];
    __shared__ double w_s2d[16];
    #pragma unroll
    for (int off = 16; off > 0; off >>= 1) {
        dnrm += __shfl_down_sync(0xFFFFFFFFu, dnrm, off);
        ds2  += __shfl_down_sync(0xFFFFFFFFu, ds2, off);
    }
    if ((t & 31) == 0) { w_nrm[t >> 5] = dnrm; w_s2d[t >> 5] = ds2; }
    __syncthreads();

    if (t == 0) {
        double NS = 0.0, S2 = 0.0;
        #pragma unroll
        for (int k = 0; k < 16; k++) { NS += w_nrm[k]; S2 += w_s2d[k]; }
        const double N = (double)N_ROWS;
        const double C = (double)N_COLS;
        double total = (2.0 * N * S2 - 2.0 * NS) / C;
        out[0] = (float)(total / (N * (N - 1.0)));
    }
}

extern "C" void kernel_launch(void* const* d_in, const int* in_sizes, int n_in,
                              void* d_out, int out_size) {
    const float* A = (const float*)d_in[0];
    float* out = (float*)d_out;
    (void)in_sizes; (void)n_in; (void)out_size;

    pass1_kernel<<<GRID1, BLK>>>(A);
    pass2_kernel<<<1, 512>>>(out);
}